// round 17
// baseline (speedup 1.0000x reference)
#include <cuda_runtime.h>
#include <cstdint>

#define VOCAB   32000
#define VWORDS  8000          // VOCAB / 4 (float4 words), < 2^13
#define TPB     512
#define SWORDS  512           // float4 words per stage (8 KB)
#define NSTAGES 16
#define DEPTH   4
#define NBINS   1024          // 10-bit bins (half-octave)
#define QCAP    128           // max gathered quads (-> 512 candidates)
#define MCAP    192           // max compact (element-level) candidates
#define GRIDP   296           // persistent grid (148 SMs x 2 blocks)

typedef unsigned long long u64;
typedef unsigned int       u32;

__device__ int g_done_ctr = 0;

__device__ __forceinline__ u32 f2s(float f) {
    u32 b = __float_as_uint(f);
    return (b & 0x80000000u) ? ~b : (b | 0x80000000u);
}

__device__ __forceinline__ u32 block_scan_u32(u32 v, u32* smem16, int tid) {
    int lane = tid & 31, wid = tid >> 5;
    u32 x = v;
#pragma unroll
    for (int o = 1; o < 32; o <<= 1) {
        u32 t = __shfl_up_sync(0xffffffffu, x, o);
        if (lane >= o) x += t;
    }
    if (lane == 31) smem16[wid] = x;
    __syncthreads();
    if (wid == 0) {
        u32 w = (lane < 16) ? smem16[lane] : 0u;
#pragma unroll
        for (int o = 1; o < 16; o <<= 1) {
            u32 t = __shfl_up_sync(0xffffffffu, w, o);
            if (lane >= o) w += t;
        }
        if (lane < 16) smem16[lane] = w;
    }
    __syncthreads();
    return x + (wid ? smem16[wid - 1] : 0u);
}

// branchless descending top-5 insert; alternate int/float minmax pipes.
__device__ __forceinline__ void ins5(u32 k, u32 (&tv)[5]) {
#pragma unroll
    for (int q = 0; q < 5; q++) {
        if (q & 1) {
            float a = __uint_as_float(tv[q]), b = __uint_as_float(k);
            float hi = fmaxf(a, b), lo = fminf(a, b);
            tv[q] = __float_as_uint(hi); k = __float_as_uint(lo);
        } else {
            u32 hi = max(tv[q], k), lo = min(tv[q], k);
            tv[q] = hi; k = lo;
        }
    }
}

__device__ __forceinline__ float ex2f(float y) {
    float r;
    asm("ex2.approx.f32 %0, %1;" : "=f"(r) : "f"(y));
    return r;
}

__device__ __forceinline__ void proc4(float4 v, int j, float c1,
                                      float& z0, float& z1, float& z2, float& z3,
                                      u32 (&tv)[5]) {
    float e0 = ex2f(v.x * c1), e1 = ex2f(v.y * c1);
    float e2 = ex2f(v.z * c1), e3 = ex2f(v.w * c1);
    z0 += e0; z1 += e1; z2 += e2; z3 += e3;
    float m = fmaxf(fmaxf(e0, e1), fmaxf(e2, e3));
    u32 k = (__float_as_uint(m) & 0xFFFFE000u) | (u32)j;
    ins5(k, tv);
}

__global__ __launch_bounds__(TPB, 2)
void sampler_row_kernel(const float* __restrict__ logits,
                        const float* __restrict__ gumbel,
                        const float* __restrict__ temp_p,
                        const float* __restrict__ topp_p,
                        const int*   __restrict__ topk_p,
                        const float* __restrict__ thr_p,
                        float* __restrict__ out, int N)
{
    __shared__ float4 s_stage[DEPTH][SWORDS];   // 32 KB (stream only)
    __shared__ u32    s_hist[NBINS];            // 4 KB (tier-1)
    __shared__ u32    s_hist2[NBINS];           // 4 KB (tier-2)
    __shared__ u32    s_g32[QCAP];
    __shared__ u64    s_ckey[MCAP];
    __shared__ float  s_cexp[MCAP];
    __shared__ float  s_cscore[MCAP];
    __shared__ int    s_cidx[MCAP];
    __shared__ u32    s_t16[16];
    __shared__ u64    s_red64[16];
    __shared__ float  s_redf[16];
    __shared__ int    s_bin, s_gcnt, s_cnt2, s_last;

    const int tid  = threadIdx.x;
    const int wid  = tid >> 5;
    const int lane = tid & 31;
    const int G    = gridDim.x;

    const float invT = 1.0f / (*temp_p);
    const float c1   = 1.44269504088896341f * invT;
    const float topP = *topp_p;
    int Kw = *topk_p;
    Kw = max(1, min(Kw, 512));
    const int KQ = min(Kw, QCAP);
    const int Ke = min(Kw, 128);

    const u32 sbase = (u32)__cvta_generic_to_shared(&s_stage[0][0]) + (u32)tid * 16u;

#define ISSUE_FULL(ptr, s)                                                    \
    do {                                                                      \
        u32 _dst = sbase + (u32)(((s) & (DEPTH - 1)) * SWORDS * 16);          \
        asm volatile("cp.async.cg.shared.global [%0], [%1], 16;"              \
                     :: "r"(_dst), "l"((ptr) + (s) * SWORDS + tid));          \
        asm volatile("cp.async.commit_group;");                               \
    } while (0)

#define ISSUE_TAIL(ptr, s)                                                    \
    do {                                                                      \
        u32 _dst = sbase + (u32)(((s) & (DEPTH - 1)) * SWORDS * 16);          \
        if ((s) * SWORDS + tid < VWORDS)                                      \
            asm volatile("cp.async.cg.shared.global [%0], [%1], 16;"          \
                         :: "r"(_dst), "l"((ptr) + (s) * SWORDS + tid));      \
        asm volatile("cp.async.commit_group;");                               \
    } while (0)

#define COMMIT_EMPTY() asm volatile("cp.async.commit_group;")

    // ---- epilogue chunks (operate on PREVIOUS row: tvp/zp/prow) ----
#define EPI_C1()                                                              \
    do {                                                                      \
        float zs = zp;                                                        \
        _Pragma("unroll")                                                     \
        for (int off = 16; off; off >>= 1)                                    \
            zs += __shfl_down_sync(0xffffffffu, zs, off);                     \
        if (lane == 0) s_redf[wid] = zs;                                      \
        __syncthreads();                                                      \
        if (tid == 0) {                                                       \
            float z = 0.0f;                                                   \
            for (int w = 0; w < 16; w++) z += s_redf[w];                      \
            s_redf[0] = z;                                                    \
        }                                                                     \
        _Pragma("unroll")                                                     \
        for (int q = 0; q < 5; q++)                                           \
            atomicAdd(&s_hist[tvp[q] >> 22], 1u);                             \
        __syncthreads();                                                      \
        e_Z = s_redf[0];                                                      \
    } while (0)

#define EPI_C2()                                                              \
    do {                                                                      \
        u32 c2[2]; u32 tsum = 0;                                              \
        _Pragma("unroll")                                                     \
        for (int q = 0; q < 2; q++) {                                         \
            int bin = (NBINS - 1) - (tid * 2 + q);                            \
            c2[q] = s_hist[bin];                                              \
            tsum += c2[q];                                                    \
        }                                                                     \
        u32 incl = block_scan_u32(tsum, s_t16, tid);                          \
        u32 cum = incl - tsum;                                                \
        _Pragma("unroll")                                                     \
        for (int q = 0; q < 2; q++) {                                         \
            if (cum < (u32)KQ && cum + c2[q] >= (u32)KQ)                      \
                s_bin = (NBINS - 1) - (tid * 2 + q);                          \
            cum += c2[q];                                                     \
        }                                                                     \
        __syncthreads();                                                      \
        int binSel = s_bin;                                                   \
        _Pragma("unroll")                                                     \
        for (int q = 0; q < 5; q++) {                                         \
            u32 key = tvp[q];                                                 \
            if ((int)(key >> 22) >= binSel) {                                 \
                int pos = atomicAdd(&s_gcnt, 1);                              \
                if (pos < QCAP) s_g32[pos] = key;                             \
            }                                                                 \
        }                                                                     \
        __syncthreads();                                                      \
        e_gex = min(s_gcnt, QCAP) * 4;                                        \
    } while (0)

#define EPI_C3()                                                              \
    do {                                                                      \
        if (tid < e_gex) {                                                    \
            u32 qk = s_g32[tid >> 2];                                         \
            e_myidx = ((int)(qk & 0x1FFFu)) * 4 + (tid & 3);                  \
            e_lx  = __ldg(prow_lg + e_myidx);                                 \
            e_myg = __ldg(prow_gm + e_myidx);                                 \
        }                                                                     \
    } while (0)

#define EPI_C4()                                                              \
    do {                                                                      \
        if (tid < e_gex) {                                                    \
            float myx = e_lx * invT;                                          \
            e_mye = __expf(myx);                                              \
            e_mybits = f2s(myx);                                              \
            e_myk = (((u64)e_mybits) << 32) | (u32)(VOCAB - e_myidx);         \
            e_score = myx + e_myg;                                            \
            atomicAdd(&s_hist2[e_mybits >> 22], 1u);                          \
        }                                                                     \
        __syncthreads();                                                      \
        u32 c2[2]; u32 tsum = 0;                                              \
        _Pragma("unroll")                                                     \
        for (int q = 0; q < 2; q++) {                                         \
            int bin = (NBINS - 1) - (tid * 2 + q);                            \
            c2[q] = s_hist2[bin];                                             \
            tsum += c2[q];                                                    \
        }                                                                     \
        u32 incl = block_scan_u32(tsum, s_t16, tid);                          \
        u32 cum = incl - tsum;                                                \
        _Pragma("unroll")                                                     \
        for (int q = 0; q < 2; q++) {                                         \
            if (cum < (u32)Ke && cum + c2[q] >= (u32)Ke)                      \
                s_bin = (NBINS - 1) - (tid * 2 + q);                          \
            cum += c2[q];                                                     \
        }                                                                     \
        __syncthreads();                                                      \
        int binSel2 = s_bin;                                                  \
        if (tid < e_gex && (int)(e_mybits >> 22) >= binSel2) {                \
            int pos = atomicAdd(&s_cnt2, 1);                                  \
            if (pos < MCAP) {                                                 \
                s_ckey[pos]   = e_myk;                                        \
                s_cexp[pos]   = e_mye;                                        \
                s_cscore[pos] = e_score;                                      \
                s_cidx[pos]   = e_myidx;                                      \
            }                                                                 \
        }                                                                     \
        __syncthreads();                                                      \
        e_mcnt = min(s_cnt2, MCAP);                                           \
    } while (0)

#define EPI_C5()                                                              \
    do {                                                                      \
        float zc = 0.0f; u64 best = 0ull;                                     \
        if (tid < e_mcnt) {                                                   \
            u64 mk = s_ckey[tid];                                             \
            int R = 0; float S = 0.0f;                                        \
            _Pragma("unroll 4")                                               \
            for (int j = 0; j < e_mcnt; j++) {                                \
                u64 kj = s_ckey[j];                                           \
                bool gt = kj > mk;                                            \
                R += gt ? 1 : 0;                                              \
                S += gt ? s_cexp[j] : 0.0f;                                   \
            }                                                                 \
            if (R < Kw && S <= topP * e_Z) {                                  \
                zc = s_cexp[tid];                                             \
                best = (((u64)f2s(s_cscore[tid])) << 32) | (u32)tid;          \
            }                                                                 \
        }                                                                     \
        _Pragma("unroll")                                                     \
        for (int off = 16; off; off >>= 1) {                                  \
            zc += __shfl_down_sync(0xffffffffu, zc, off);                     \
            u64 o = __shfl_down_sync(0xffffffffu, best, off);                 \
            if (o > best) best = o;                                           \
        }                                                                     \
        if (lane == 0) { s_redf[wid] = zc; s_red64[wid] = best; }             \
        __syncthreads();                                                      \
        if (tid == 0) {                                                       \
            float Zp = 0.0f; u64 b = 0ull;                                    \
            for (int w = 0; w < 16; w++) {                                    \
                Zp += s_redf[w];                                              \
                if (s_red64[w] > b) b = s_red64[w];                           \
            }                                                                 \
            int sel = (int)(u32)b;                                            \
            float conf = s_cexp[sel] / Zp;                                    \
            out[prow]         = conf;                                         \
            out[N + prow]     = (float)s_cidx[sel];                           \
            out[2 * N + prow] = conf;                                         \
            __threadfence();                                                  \
            int prev = atomicAdd(&g_done_ctr, 1);                             \
            s_last = (prev == N - 1) ? 1 : 0;                                 \
        }                                                                     \
        __syncthreads();                                                      \
        if (s_last) {                                                         \
            __threadfence();                                                  \
            const float thr = *thr_p;                                         \
            u64 fb = 0ull; int anyl = 0;                                      \
            float cv[4];                                                      \
            _Pragma("unroll")                                                 \
            for (int q = 0; q < 4; q++) {                                     \
                int r = tid + q * TPB;                                        \
                float c = (r < N) ? out[r] : -1.0f;                           \
                cv[q] = c;                                                    \
                if (r < N) {                                                  \
                    if (c > thr) anyl = 1;                                    \
                    u64 k = (((u64)f2s(c)) << 32) | (u32)(N - 1 - r);         \
                    if (k > fb) fb = k;                                       \
                }                                                             \
            }                                                                 \
            _Pragma("unroll")                                                 \
            for (int off = 16; off; off >>= 1) {                              \
                u64 o = __shfl_down_sync(0xffffffffu, fb, off);               \
                if (o > fb) fb = o;                                           \
            }                                                                 \
            int anyw = __any_sync(0xffffffffu, anyl);                         \
            if (lane == 0) { s_red64[wid] = fb; s_t16[wid] = (u32)anyw; }     \
            __syncthreads();                                                  \
            if (tid == 0) {                                                   \
                u64 b = 0ull; u32 a = 0;                                      \
                for (int w = 0; w < 16; w++) {                                \
                    if (s_red64[w] > b) b = s_red64[w];                       \
                    a |= s_t16[w];                                            \
                }                                                             \
                s_red64[0] = b;                                               \
                s_t16[0] = a;                                                 \
                g_done_ctr = 0;                                               \
            }                                                                 \
            __syncthreads();                                                  \
            const int argrow = N - 1 - (int)(u32)s_red64[0];                  \
            const int anyh = (int)s_t16[0];                                   \
            _Pragma("unroll")                                                 \
            for (int q = 0; q < 4; q++) {                                     \
                int r = tid + q * TPB;                                        \
                if (r < N)                                                    \
                    out[3 * N + r] = anyh ? ((cv[q] > thr) ? 1.0f : 0.0f)     \
                                          : ((r == argrow) ? 1.0f : 0.0f);    \
            }                                                                 \
        }                                                                     \
        /* reset scratch for next row's epilogue */                           \
        _Pragma("unroll")                                                     \
        for (int q = 0; q < NBINS / TPB; q++) {                               \
            s_hist[tid + q * TPB]  = 0u;                                      \
            s_hist2[tid + q * TPB] = 0u;                                      \
        }                                                                     \
        if (tid == 0) { s_gcnt = 0; s_cnt2 = 0; }                             \
        __syncthreads();                                                      \
    } while (0)

    // initial scratch state
#pragma unroll
    for (int q = 0; q < NBINS / TPB; q++) {
        s_hist[tid + q * TPB]  = 0u;
        s_hist2[tid + q * TPB] = 0u;
    }
    if (tid == 0) { s_gcnt = 0; s_cnt2 = 0; }
    __syncthreads();

    // prologue: prefetch first row's stages 0..3
    {
        const float4* rp0 = (const float4*)(logits + (size_t)blockIdx.x * VOCAB);
        ISSUE_FULL(rp0, 0); ISSUE_FULL(rp0, 1);
        ISSUE_FULL(rp0, 2); ISSUE_FULL(rp0, 3);
    }

    bool have_prev = false;
    int  prow = 0;
    u32  tvp[5] = {0, 0, 0, 0, 0};
    float zp = 0.0f;

    for (int row = blockIdx.x; row < N; row += G) {
        const float4* rp = (const float4*)(logits + (size_t)row * VOCAB);
        const bool hasnext = (row + G) < N;
        const float4* rpn = hasnext
            ? (const float4*)(logits + (size_t)(row + G) * VOCAB) : rp;

        const float* prow_lg = logits + (size_t)prow * VOCAB;
        const float* prow_gm = gumbel + (size_t)prow * VOCAB;

        u32 tv[5];
#pragma unroll
        for (int q = 0; q < 5; q++) tv[q] = 0u;
        float z0 = 0.f, z1 = 0.f, z2 = 0.f, z3 = 0.f;

        // epilogue cross-chunk state (for PREVIOUS row)
        float e_Z = 0.f, e_lx = 0.f, e_myg = 0.f, e_mye = 0.f, e_score = 0.f;
        u64 e_myk = 0ull; int e_myidx = 0, e_gex = 0, e_mcnt = 0; u32 e_mybits = 0;

#pragma unroll
        for (int s = 0; s < NSTAGES; s++) {
            asm volatile("cp.async.wait_group %0;" :: "n"(DEPTH - 1));
            int j = s * SWORDS + tid;
            if (s < NSTAGES - 1 || j < VWORDS) {
                float4 v = s_stage[s & (DEPTH - 1)][tid];
                proc4(v, j, c1, z0, z1, z2, z3, tv);
            }
            // lookahead: current row stages 4..15, then next row 0..3
            if (s < NSTAGES - DEPTH) {
                if (s + DEPTH < NSTAGES - 1) ISSUE_FULL(rp, s + DEPTH);
                else                         ISSUE_TAIL(rp, NSTAGES - 1);
            } else {
                if (hasnext) ISSUE_FULL(rpn, s - (NSTAGES - DEPTH));
                else         COMMIT_EMPTY();
            }
            // interleaved epilogue of previous row
            if (have_prev) {
                if (s == 3)  EPI_C1();
                if (s == 6)  EPI_C2();
                if (s == 8)  EPI_C3();
                if (s == 10) EPI_C4();
                if (s == 14) EPI_C5();
            }
        }

        // snapshot this row's stream results for its (deferred) epilogue
        zp = (z0 + z1) + (z2 + z3);
#pragma unroll
        for (int q = 0; q < 5; q++) tvp[q] = tv[q];
        prow = row;
        have_prev = true;
    }

    // drain: epilogue for the final row of this block
    {
        const float* prow_lg = logits + (size_t)prow * VOCAB;
        const float* prow_gm = gumbel + (size_t)prow * VOCAB;
        float e_Z = 0.f, e_lx = 0.f, e_myg = 0.f, e_mye = 0.f, e_score = 0.f;
        u64 e_myk = 0ull; int e_myidx = 0, e_gex = 0, e_mcnt = 0; u32 e_mybits = 0;
        EPI_C1();
        EPI_C2();
        EPI_C3();
        EPI_C4();
        EPI_C5();
    }

    asm volatile("cp.async.wait_group 0;");
}

extern "C" void kernel_launch(void* const* d_in, const int* in_sizes, int n_in,
                              void* d_out, int out_size)
{
    const float* logits = (const float*)d_in[0];
    const float* gumbel = (const float*)d_in[1];
    const float* temp   = (const float*)d_in[2];
    const float* topp   = (const float*)d_in[3];
    const int*   topk   = (const int*)  d_in[4];
    const float* thr    = (const float*)d_in[5];

    int N = in_sizes[0] / VOCAB;
    float* out = (float*)d_out;

    int G = (N < GRIDP) ? N : GRIDP;
    sampler_row_kernel<<<G, TPB>>>(logits, gumbel, temp, topp, topk, thr, out, N);
}